// round 1
// baseline (speedup 1.0000x reference)
#include <cuda_runtime.h>
#include <cuda_bf16.h>

#define NB 64      // batch
#define NL 512     // sequence length
#define ND 300     // embed dim
#define NC 128     // channels
#define TCHUNKS 8
#define TOK_PER (NL / TCHUNKS)   // 64 tokens per block

// Scratch (allocation-free rule: __device__ globals)
__device__ float g_acc[NB * 3 * ND];   // g[b][k][d]
__device__ float g_coef[3 * NL];       // A_k[t]
__device__ float g_Sk[3];              // sum of wk

// ---------------------------------------------------------------------------
// Kernel 0: per-token coefficients A_k[t], window-weight sums S_k, zero g_acc
// ---------------------------------------------------------------------------
__global__ __launch_bounds__(512) void prep_kernel(const float* __restrict__ fc3_w,
                                                   const float* __restrict__ fc4_w,
                                                   const float* __restrict__ fc5_w) {
    const int t = threadIdx.x;  // 512 threads == NL
    const float* wks[3] = {fc3_w, fc4_w, fc5_w};

    // A_k[t] = sum_{l = max(0, t-k+1)}^{min(t, L-k-1)} wk[l]
    for (int kk = 0; kk < 3; kk++) {
        const int k = kk + 3;
        int lo = t - k + 1; if (lo < 0) lo = 0;
        int hi = t; const int lim = NL - k - 1; if (hi > lim) hi = lim;
        float s = 0.f;
        for (int l = lo; l <= hi; l++) s += wks[kk][l];
        g_coef[kk * NL + t] = s;
    }

    // zero the accumulator (graph replays re-zero every call — deterministic)
    for (int i = t; i < NB * 3 * ND; i += 512) g_acc[i] = 0.f;

    // S_k = sum over wk (length L-k)
    __shared__ float red[512];
    for (int kk = 0; kk < 3; kk++) {
        const int k = kk + 3;
        red[t] = (t < NL - k) ? wks[kk][t] : 0.f;
        __syncthreads();
        for (int off = 256; off > 0; off >>= 1) {
            if (t < off) red[t] += red[t + off];
            __syncthreads();
        }
        if (t == 0) g_Sk[kk] = red[0];
        __syncthreads();
    }
}

// ---------------------------------------------------------------------------
// Kernel 1: embedding gather + weighted reduction into g[b][k][d]
// grid = NB * TCHUNKS blocks, 320 threads (d-lane, guard d<300)
// ---------------------------------------------------------------------------
__global__ __launch_bounds__(320) void gather_kernel(const int* __restrict__ x,
                                                     const float* __restrict__ embed_w) {
    const int b = blockIdx.x >> 3;        // / TCHUNKS
    const int chunk = blockIdx.x & 7;     // % TCHUNKS

    __shared__ int   sidx[TOK_PER];
    __shared__ float sc0[TOK_PER], sc1[TOK_PER], sc2[TOK_PER];

    const int tid = threadIdx.x;
    if (tid < TOK_PER) {
        const int t = chunk * TOK_PER + tid;
        sidx[tid] = x[b * NL + t];
        sc0[tid]  = g_coef[0 * NL + t];
        sc1[tid]  = g_coef[1 * NL + t];
        sc2[tid]  = g_coef[2 * NL + t];
    }
    __syncthreads();

    const int d = tid;
    if (d < ND) {
        float a0 = 0.f, a1 = 0.f, a2 = 0.f;
        #pragma unroll 4
        for (int j = 0; j < TOK_PER; j++) {
            const float v = __ldg(&embed_w[sidx[j] * ND + d]);  // coalesced across d
            a0 = fmaf(sc0[j], v, a0);
            a1 = fmaf(sc1[j], v, a1);
            a2 = fmaf(sc2[j], v, a2);
        }
        atomicAdd(&g_acc[(b * 3 + 0) * ND + d], a0);
        atomicAdd(&g_acc[(b * 3 + 1) * ND + d], a1);
        atomicAdd(&g_acc[(b * 3 + 2) * ND + d], a2);
    }
}

// ---------------------------------------------------------------------------
// Kernel 2: epilogue — sim = conv(g) + biases, then out = h @ fc_w^T + fc_b
// grid = NB blocks, NC threads
// ---------------------------------------------------------------------------
__global__ __launch_bounds__(128) void final_kernel(const float* __restrict__ conv_w,
                                                    const float* __restrict__ conv_b,
                                                    const float* __restrict__ fc3_b,
                                                    const float* __restrict__ fc4_b,
                                                    const float* __restrict__ fc5_b,
                                                    const float* __restrict__ fc_w,
                                                    const float* __restrict__ fc_b,
                                                    float* __restrict__ out) {
    const int b = blockIdx.x;
    const int c = threadIdx.x;

    __shared__ float sg[3 * ND];   // g[b]
    __shared__ float sh[3 * NC];   // h[b]

    for (int i = c; i < 3 * ND; i += NC) sg[i] = g_acc[b * 3 * ND + i];
    __syncthreads();

    const float bks[3] = {fc3_b[0], fc4_b[0], fc5_b[0]};
    const float cb = conv_b[c];
    for (int kk = 0; kk < 3; kk++) {
        float s = 0.f;
        const float* cw = conv_w + c * ND;
        const float* gg = sg + kk * ND;
        #pragma unroll 4
        for (int d = 0; d < ND; d++) s = fmaf(cw[d], gg[d], s);
        sh[kk * NC + c] = s + cb * g_Sk[kk] + bks[kk];
    }
    __syncthreads();

    float o = fc_b[c];
    const float* fw = fc_w + c * 3 * NC;
    #pragma unroll 4
    for (int j = 0; j < 3 * NC; j++) o = fmaf(fw[j], sh[j], o);
    out[b * NC + c] = o;
}

// ---------------------------------------------------------------------------
extern "C" void kernel_launch(void* const* d_in, const int* in_sizes, int n_in,
                              void* d_out, int out_size) {
    const int*   x       = (const int*)  d_in[0];
    const float* embed_w = (const float*)d_in[1];
    const float* conv_w  = (const float*)d_in[2];
    const float* conv_b  = (const float*)d_in[3];
    const float* fc3_w   = (const float*)d_in[4];
    const float* fc3_b   = (const float*)d_in[5];
    const float* fc4_w   = (const float*)d_in[6];
    const float* fc4_b   = (const float*)d_in[7];
    const float* fc5_w   = (const float*)d_in[8];
    const float* fc5_b   = (const float*)d_in[9];
    const float* fc_w    = (const float*)d_in[10];
    const float* fc_b    = (const float*)d_in[11];
    float* out = (float*)d_out;

    prep_kernel<<<1, 512>>>(fc3_w, fc4_w, fc5_w);
    gather_kernel<<<NB * TCHUNKS, 320>>>(x, embed_w);
    final_kernel<<<NB, NC>>>(conv_w, conv_b, fc3_b, fc4_b, fc5_b, fc_w, fc_b, out);
}

// round 2
// speedup vs baseline: 2.7291x; 2.7291x over previous
#include <cuda_runtime.h>
#include <cuda_bf16.h>

#define NB 64      // batch
#define NL 512     // sequence length
#define ND 300     // embed dim
#define ND4 75     // float4 lanes per row
#define NC 128     // channels
#define CH 16      // token chunks per batch
#define TPC (NL / CH)    // 32 tokens per block
#define WAYS 4
#define JPER (TPC / WAYS) // 8 tokens per way

// Partial sums: g_part[b][ch][k][d]  (atomic-free; final kernel reduces chunks)
__device__ float g_part[NB * CH * 3 * ND];

// ---------------------------------------------------------------------------
// Kernel 1: embedding gather + weighted partial reduction.
// grid = NB*CH blocks, 320 threads = 80 float4 d-lanes x 4 token-ways.
// Per-token coefficients A_k[t] computed inline (<=5 cached loads each).
// ---------------------------------------------------------------------------
__global__ __launch_bounds__(320) void gather_kernel(
    const int*   __restrict__ x,
    const float* __restrict__ embed_w,
    const float* __restrict__ fc3_w,
    const float* __restrict__ fc4_w,
    const float* __restrict__ fc5_w)
{
    const int b     = blockIdx.x / CH;
    const int chunk = blockIdx.x % CH;

    __shared__ int    sidx[TPC];
    __shared__ float  sc[3][TPC];
    __shared__ float4 sred[WAYS][3][80];   // 15360 B

    const int tid = threadIdx.x;
    const int d4  = tid % 80;
    const int y   = tid / 80;

    if (tid < TPC) {
        const int t = chunk * TPC + tid;
        sidx[tid] = x[b * NL + t];
        const float* wks[3] = {fc3_w, fc4_w, fc5_w};
        #pragma unroll
        for (int kk = 0; kk < 3; kk++) {
            const int k = kk + 3;
            int lo = t - k + 1; if (lo < 0) lo = 0;
            int hi = t; const int lim = NL - k - 1; if (hi > lim) hi = lim;
            float s = 0.f;
            for (int l = lo; l <= hi; l++) s += wks[kk][l];
            sc[kk][tid] = s;
        }
    }
    __syncthreads();

    float4 a0 = make_float4(0.f, 0.f, 0.f, 0.f);
    float4 a1 = a0, a2 = a0;

    if (d4 < ND4) {
        const float4* emb4 = (const float4*)embed_w;
        #pragma unroll
        for (int j = 0; j < JPER; j++) {
            const int jj = y * JPER + j;
            const float4 v = __ldg(&emb4[sidx[jj] * ND4 + d4]);
            const float c0 = sc[0][jj], c1 = sc[1][jj], c2 = sc[2][jj];
            a0.x = fmaf(c0, v.x, a0.x); a0.y = fmaf(c0, v.y, a0.y);
            a0.z = fmaf(c0, v.z, a0.z); a0.w = fmaf(c0, v.w, a0.w);
            a1.x = fmaf(c1, v.x, a1.x); a1.y = fmaf(c1, v.y, a1.y);
            a1.z = fmaf(c1, v.z, a1.z); a1.w = fmaf(c1, v.w, a1.w);
            a2.x = fmaf(c2, v.x, a2.x); a2.y = fmaf(c2, v.y, a2.y);
            a2.z = fmaf(c2, v.z, a2.z); a2.w = fmaf(c2, v.w, a2.w);
        }
    }
    sred[y][0][d4] = a0;
    sred[y][1][d4] = a1;
    sred[y][2][d4] = a2;
    __syncthreads();

    // 240 threads reduce the 4 ways: tid -> (kk, d4)
    if (tid < 240) {
        const int kk = tid / 80;
        const int dd = tid % 80;
        if (dd < ND4) {
            float4 s = sred[0][kk][dd];
            #pragma unroll
            for (int w = 1; w < WAYS; w++) {
                const float4 v = sred[w][kk][dd];
                s.x += v.x; s.y += v.y; s.z += v.z; s.w += v.w;
            }
            float4* dst = (float4*)&g_part[((b * CH + chunk) * 3 + kk) * ND];
            dst[dd] = s;
        }
    }
}

// ---------------------------------------------------------------------------
// Kernel 2: reduce chunk partials, compute S_k, conv epilogue, fc epilogue.
// grid = NB blocks, NC=128 threads (thread c = output channel).
// ---------------------------------------------------------------------------
__global__ __launch_bounds__(128) void final_kernel(
    const float* __restrict__ conv_w,
    const float* __restrict__ conv_b,
    const float* __restrict__ fc3_w,
    const float* __restrict__ fc3_b,
    const float* __restrict__ fc4_w,
    const float* __restrict__ fc4_b,
    const float* __restrict__ fc5_w,
    const float* __restrict__ fc5_b,
    const float* __restrict__ fc_w,
    const float* __restrict__ fc_b,
    float* __restrict__ out)
{
    const int b = blockIdx.x;
    const int c = threadIdx.x;

    __shared__ float sg[3 * ND];    // reduced g[b]
    __shared__ float sh[3 * NC];    // h[b]
    __shared__ float sred[NC];
    __shared__ float sSk[3];

    // Reduce the CH chunk partials into sg
    for (int i = c; i < 3 * ND; i += NC) {
        float s = 0.f;
        const float* p = &g_part[b * CH * 3 * ND + i];
        #pragma unroll
        for (int ch = 0; ch < CH; ch++) s += p[ch * 3 * ND];
        sg[i] = s;
    }

    // S_k = sum of wk (length L-k), block reduction
    const float* wks[3] = {fc3_w, fc4_w, fc5_w};
    for (int kk = 0; kk < 3; kk++) {
        const int n = NL - (kk + 3);
        float s = 0.f;
        for (int l = c; l < n; l += NC) s += wks[kk][l];
        sred[c] = s;
        __syncthreads();
        for (int off = 64; off > 0; off >>= 1) {
            if (c < off) sred[c] += sred[c + off];
            __syncthreads();
        }
        if (c == 0) sSk[kk] = sred[0];
        __syncthreads();
    }

    // conv: sh[kk][c] = conv_w[c] . g[kk]  + conv_b[c]*S_k + b_k
    {
        const float4* cw4 = (const float4*)(conv_w + c * ND);
        const float4* sg4 = (const float4*)sg;
        float s0 = 0.f, s1 = 0.f, s2 = 0.f;
        #pragma unroll 5
        for (int d4 = 0; d4 < ND4; d4++) {
            const float4 w = __ldg(&cw4[d4]);
            const float4 g0 = sg4[0 * ND4 + d4];
            const float4 g1 = sg4[1 * ND4 + d4];
            const float4 g2 = sg4[2 * ND4 + d4];
            s0 = fmaf(w.x, g0.x, s0); s0 = fmaf(w.y, g0.y, s0);
            s0 = fmaf(w.z, g0.z, s0); s0 = fmaf(w.w, g0.w, s0);
            s1 = fmaf(w.x, g1.x, s1); s1 = fmaf(w.y, g1.y, s1);
            s1 = fmaf(w.z, g1.z, s1); s1 = fmaf(w.w, g1.w, s1);
            s2 = fmaf(w.x, g2.x, s2); s2 = fmaf(w.y, g2.y, s2);
            s2 = fmaf(w.z, g2.z, s2); s2 = fmaf(w.w, g2.w, s2);
        }
        const float cb = conv_b[c];
        sh[0 * NC + c] = s0 + cb * sSk[0] + fc3_b[0];
        sh[1 * NC + c] = s1 + cb * sSk[1] + fc4_b[0];
        sh[2 * NC + c] = s2 + cb * sSk[2] + fc5_b[0];
    }
    __syncthreads();

    // out[b][c] = fc_w[c] . h + fc_b[c]
    {
        const float4* fw4 = (const float4*)(fc_w + c * 3 * NC);
        const float4* sh4 = (const float4*)sh;
        float o = fc_b[c];
        #pragma unroll 6
        for (int j4 = 0; j4 < (3 * NC) / 4; j4++) {
            const float4 w = __ldg(&fw4[j4]);
            const float4 h = sh4[j4];
            o = fmaf(w.x, h.x, o); o = fmaf(w.y, h.y, o);
            o = fmaf(w.z, h.z, o); o = fmaf(w.w, h.w, o);
        }
        out[b * NC + c] = o;
    }
}

// ---------------------------------------------------------------------------
extern "C" void kernel_launch(void* const* d_in, const int* in_sizes, int n_in,
                              void* d_out, int out_size) {
    const int*   x       = (const int*)  d_in[0];
    const float* embed_w = (const float*)d_in[1];
    const float* conv_w  = (const float*)d_in[2];
    const float* conv_b  = (const float*)d_in[3];
    const float* fc3_w   = (const float*)d_in[4];
    const float* fc3_b   = (const float*)d_in[5];
    const float* fc4_w   = (const float*)d_in[6];
    const float* fc4_b   = (const float*)d_in[7];
    const float* fc5_w   = (const float*)d_in[8];
    const float* fc5_b   = (const float*)d_in[9];
    const float* fc_w    = (const float*)d_in[10];
    const float* fc_b    = (const float*)d_in[11];
    float* out = (float*)d_out;

    gather_kernel<<<NB * CH, 320>>>(x, embed_w, fc3_w, fc4_w, fc5_w);
    final_kernel<<<NB, NC>>>(conv_w, conv_b, fc3_w, fc3_b, fc4_w, fc4_b,
                             fc5_w, fc5_b, fc_w, fc_b, out);
}

// round 3
// speedup vs baseline: 2.9154x; 1.0683x over previous
#include <cuda_runtime.h>
#include <cuda_bf16.h>

#define NB 64      // batch
#define NL 512     // sequence length
#define ND 300     // embed dim
#define ND4 75     // float4 lanes per row
#define NC 128     // channels
#define CH 16      // token chunks per batch
#define TPC (NL / CH)    // 32 tokens per block
#define WAYS 4
#define JPER (TPC / WAYS) // 8 tokens per way

// Partial sums: g_part[b][ch][k][d]  (atomic-free; final kernel reduces chunks)
__device__ float g_part[NB * CH * 3 * ND];

// ---------------------------------------------------------------------------
// Kernel 1: embedding gather + weighted partial reduction.
// grid = NB*CH blocks, 320 threads = 80 float4 d-lanes x 4 token-ways.
// ---------------------------------------------------------------------------
__global__ __launch_bounds__(320) void gather_kernel(
    const int*   __restrict__ x,
    const float* __restrict__ embed_w,
    const float* __restrict__ fc3_w,
    const float* __restrict__ fc4_w,
    const float* __restrict__ fc5_w)
{
    const int b     = blockIdx.x / CH;
    const int chunk = blockIdx.x % CH;

    __shared__ int    sidx[TPC];
    __shared__ float  sc[3][TPC];
    __shared__ float4 sred[WAYS][3][80];

    const int tid = threadIdx.x;
    const int d4  = tid % 80;
    const int y   = tid / 80;

    if (tid < TPC) {
        const int t = chunk * TPC + tid;
        sidx[tid] = x[b * NL + t];
        const float* wks[3] = {fc3_w, fc4_w, fc5_w};
        #pragma unroll
        for (int kk = 0; kk < 3; kk++) {
            const int k = kk + 3;
            int lo = t - k + 1; if (lo < 0) lo = 0;
            int hi = t; const int lim = NL - k - 1; if (hi > lim) hi = lim;
            float s = 0.f;
            for (int l = lo; l <= hi; l++) s += wks[kk][l];
            sc[kk][tid] = s;
        }
    }
    __syncthreads();

    float4 a0 = make_float4(0.f, 0.f, 0.f, 0.f);
    float4 a1 = a0, a2 = a0;

    if (d4 < ND4) {
        const float4* emb4 = (const float4*)embed_w;
        #pragma unroll
        for (int j = 0; j < JPER; j++) {
            const int jj = y * JPER + j;
            const float4 v = __ldg(&emb4[sidx[jj] * ND4 + d4]);
            const float c0 = sc[0][jj], c1 = sc[1][jj], c2 = sc[2][jj];
            a0.x = fmaf(c0, v.x, a0.x); a0.y = fmaf(c0, v.y, a0.y);
            a0.z = fmaf(c0, v.z, a0.z); a0.w = fmaf(c0, v.w, a0.w);
            a1.x = fmaf(c1, v.x, a1.x); a1.y = fmaf(c1, v.y, a1.y);
            a1.z = fmaf(c1, v.z, a1.z); a1.w = fmaf(c1, v.w, a1.w);
            a2.x = fmaf(c2, v.x, a2.x); a2.y = fmaf(c2, v.y, a2.y);
            a2.z = fmaf(c2, v.z, a2.z); a2.w = fmaf(c2, v.w, a2.w);
        }
    }
    sred[y][0][d4] = a0;
    sred[y][1][d4] = a1;
    sred[y][2][d4] = a2;
    __syncthreads();

    if (tid < 240) {
        const int kk = tid / 80;
        const int dd = tid % 80;
        if (dd < ND4) {
            float4 s = sred[0][kk][dd];
            #pragma unroll
            for (int w = 1; w < WAYS; w++) {
                const float4 v = sred[w][kk][dd];
                s.x += v.x; s.y += v.y; s.z += v.z; s.w += v.w;
            }
            float4* dst = (float4*)&g_part[((b * CH + chunk) * 3 + kk) * ND];
            dst[dd] = s;
        }
    }
}

// ---------------------------------------------------------------------------
// Kernel 2: reduce partials + conv + fc, all warp-per-channel COALESCED.
// grid = NB blocks, 256 threads (8 warps).
// ---------------------------------------------------------------------------
__global__ __launch_bounds__(256) void final_kernel(
    const float* __restrict__ conv_w,
    const float* __restrict__ conv_b,
    const float* __restrict__ fc3_w,
    const float* __restrict__ fc3_b,
    const float* __restrict__ fc4_w,
    const float* __restrict__ fc4_b,
    const float* __restrict__ fc5_w,
    const float* __restrict__ fc5_b,
    const float* __restrict__ fc_w,
    const float* __restrict__ fc_b,
    float* __restrict__ out)
{
    const int b    = blockIdx.x;
    const int tid  = threadIdx.x;
    const int warp = tid >> 5;
    const int lane = tid & 31;

    __shared__ float4 sg4[3 * ND4];   // 225 float4 = g[b], aligned
    __shared__ float4 sh4[3 * NC / 4]; // 96 float4 = h[b]
    __shared__ float  sSk[3];

    // Reduce the CH chunk partials into sg (float4, 16 independent LDG.128/thread)
    {
        const float4* base = (const float4*)&g_part[b * CH * 3 * ND];
        for (int i = tid; i < 3 * ND4; i += 256) {
            float4 s = make_float4(0.f, 0.f, 0.f, 0.f);
            #pragma unroll
            for (int ch = 0; ch < CH; ch++) {
                const float4 v = base[ch * (3 * ND4) + i];
                s.x += v.x; s.y += v.y; s.z += v.z; s.w += v.w;
            }
            sg4[i] = s;
        }
    }

    // S_k: one warp per k, coalesced + shuffle reduce
    if (warp < 3) {
        const float* wks[3] = {fc3_w, fc4_w, fc5_w};
        const float* w = wks[warp];
        const int n = NL - (warp + 3);
        float s = 0.f;
        for (int l = lane; l < n; l += 32) s += w[l];
        #pragma unroll
        for (int off = 16; off > 0; off >>= 1)
            s += __shfl_xor_sync(0xFFFFFFFFu, s, off);
        if (lane == 0) sSk[warp] = s;
    }
    __syncthreads();

    // conv: warp handles 16 channels; per channel lanes split d4 (coalesced)
    {
        const float4* cw4 = (const float4*)conv_w;
        #pragma unroll
        for (int ci = 0; ci < NC / 8; ci++) {
            const int c = warp * (NC / 8) + ci;
            float s0 = 0.f, s1 = 0.f, s2 = 0.f;
            for (int i = lane; i < ND4; i += 32) {
                const float4 w  = __ldg(&cw4[c * ND4 + i]);
                const float4 g0 = sg4[i];
                const float4 g1 = sg4[ND4 + i];
                const float4 g2 = sg4[2 * ND4 + i];
                s0 = fmaf(w.x, g0.x, s0); s0 = fmaf(w.y, g0.y, s0);
                s0 = fmaf(w.z, g0.z, s0); s0 = fmaf(w.w, g0.w, s0);
                s1 = fmaf(w.x, g1.x, s1); s1 = fmaf(w.y, g1.y, s1);
                s1 = fmaf(w.z, g1.z, s1); s1 = fmaf(w.w, g1.w, s1);
                s2 = fmaf(w.x, g2.x, s2); s2 = fmaf(w.y, g2.y, s2);
                s2 = fmaf(w.z, g2.z, s2); s2 = fmaf(w.w, g2.w, s2);
            }
            #pragma unroll
            for (int off = 16; off > 0; off >>= 1) {
                s0 += __shfl_xor_sync(0xFFFFFFFFu, s0, off);
                s1 += __shfl_xor_sync(0xFFFFFFFFu, s1, off);
                s2 += __shfl_xor_sync(0xFFFFFFFFu, s2, off);
            }
            if (lane == 0) {
                const float cb = conv_b[c];
                float* sh = (float*)sh4;
                sh[0 * NC + c] = s0 + cb * sSk[0] + fc3_b[0];
                sh[1 * NC + c] = s1 + cb * sSk[1] + fc4_b[0];
                sh[2 * NC + c] = s2 + cb * sSk[2] + fc5_b[0];
            }
        }
    }
    __syncthreads();

    // fc: warp handles 16 channels; per channel lanes split the 96 float4
    {
        const float4* fw4 = (const float4*)fc_w;
        #pragma unroll
        for (int ci = 0; ci < NC / 8; ci++) {
            const int c = warp * (NC / 8) + ci;
            float o = 0.f;
            #pragma unroll
            for (int i = lane; i < 96; i += 32) {
                const float4 w = __ldg(&fw4[c * 96 + i]);
                const float4 h = sh4[i];
                o = fmaf(w.x, h.x, o); o = fmaf(w.y, h.y, o);
                o = fmaf(w.z, h.z, o); o = fmaf(w.w, h.w, o);
            }
            #pragma unroll
            for (int off = 16; off > 0; off >>= 1)
                o += __shfl_xor_sync(0xFFFFFFFFu, o, off);
            if (lane == 0) out[b * NC + c] = o + fc_b[c];
        }
    }
}

// ---------------------------------------------------------------------------
extern "C" void kernel_launch(void* const* d_in, const int* in_sizes, int n_in,
                              void* d_out, int out_size) {
    const int*   x       = (const int*)  d_in[0];
    const float* embed_w = (const float*)d_in[1];
    const float* conv_w  = (const float*)d_in[2];
    const float* conv_b  = (const float*)d_in[3];
    const float* fc3_w   = (const float*)d_in[4];
    const float* fc3_b   = (const float*)d_in[5];
    const float* fc4_w   = (const float*)d_in[6];
    const float* fc4_b   = (const float*)d_in[7];
    const float* fc5_w   = (const float*)d_in[8];
    const float* fc5_b   = (const float*)d_in[9];
    const float* fc_w    = (const float*)d_in[10];
    const float* fc_b    = (const float*)d_in[11];
    float* out = (float*)d_out;

    gather_kernel<<<NB * CH, 320>>>(x, embed_w, fc3_w, fc4_w, fc5_w);
    final_kernel<<<NB, 256>>>(conv_w, conv_b, fc3_w, fc3_b, fc4_w, fc4_b,
                              fc5_w, fc5_b, fc_w, fc_b, out);
}

// round 4
// speedup vs baseline: 3.8331x; 1.3148x over previous
#include <cuda_runtime.h>
#include <cuda_bf16.h>

#define NB 64      // batch
#define NL 512     // sequence length
#define ND 300     // embed dim
#define ND4 75     // float4 lanes per row
#define NC 128     // channels
#define CH 4       // token chunks per batch
#define TPC 128    // tokens per gather block (NL/CH)
#define WAYS 4
#define JPER 32    // tokens per way (TPC/WAYS)

// Scratch (__device__ globals per allocation rules)
__device__ float4 g_part4[NB * CH * 3 * ND4];  // partial g sums, f4
__device__ float4 g_h4[NB * 96];               // h[b][384] as f4

// ---------------------------------------------------------------------------
// Kernel 1: embedding gather + weighted partial reduction.
// grid = NB*CH = 256 blocks, 320 threads = 80 f4 d-lanes x 4 token-ways.
// ---------------------------------------------------------------------------
__global__ __launch_bounds__(320) void gather_kernel(
    const int*   __restrict__ x,
    const float* __restrict__ embed_w,
    const float* __restrict__ fc3_w,
    const float* __restrict__ fc4_w,
    const float* __restrict__ fc5_w)
{
    const int b     = blockIdx.x / CH;
    const int chunk = blockIdx.x % CH;

    __shared__ int    sidx[TPC];
    __shared__ float  sc[3][TPC];
    __shared__ float4 sred[WAYS][3][80];

    const int tid = threadIdx.x;
    const int d4  = tid % 80;
    const int y   = tid / 80;

    if (tid < TPC) {
        const int t = chunk * TPC + tid;
        sidx[tid] = x[b * NL + t];
        const float* wks[3] = {fc3_w, fc4_w, fc5_w};
        #pragma unroll
        for (int kk = 0; kk < 3; kk++) {
            const int k = kk + 3;
            int lo = t - k + 1; if (lo < 0) lo = 0;
            int hi = t; const int lim = NL - k - 1; if (hi > lim) hi = lim;
            float s = 0.f;
            for (int l = lo; l <= hi; l++) s += wks[kk][l];
            sc[kk][tid] = s;
        }
    }
    __syncthreads();

    float4 a0 = make_float4(0.f, 0.f, 0.f, 0.f);
    float4 a1 = a0, a2 = a0;

    if (d4 < ND4) {
        const float4* emb4 = (const float4*)embed_w;
        #pragma unroll 4
        for (int j = 0; j < JPER; j++) {
            const int jj = y * JPER + j;
            const float4 v = __ldg(&emb4[sidx[jj] * ND4 + d4]);
            const float c0 = sc[0][jj], c1 = sc[1][jj], c2 = sc[2][jj];
            a0.x = fmaf(c0, v.x, a0.x); a0.y = fmaf(c0, v.y, a0.y);
            a0.z = fmaf(c0, v.z, a0.z); a0.w = fmaf(c0, v.w, a0.w);
            a1.x = fmaf(c1, v.x, a1.x); a1.y = fmaf(c1, v.y, a1.y);
            a1.z = fmaf(c1, v.z, a1.z); a1.w = fmaf(c1, v.w, a1.w);
            a2.x = fmaf(c2, v.x, a2.x); a2.y = fmaf(c2, v.y, a2.y);
            a2.z = fmaf(c2, v.z, a2.z); a2.w = fmaf(c2, v.w, a2.w);
        }
    }
    sred[y][0][d4] = a0;
    sred[y][1][d4] = a1;
    sred[y][2][d4] = a2;
    __syncthreads();

    if (tid < 240) {
        const int kk = tid / 80;
        const int dd = tid % 80;
        if (dd < ND4) {
            float4 s = sred[0][kk][dd];
            #pragma unroll
            for (int w = 1; w < WAYS; w++) {
                const float4 v = sred[w][kk][dd];
                s.x += v.x; s.y += v.y; s.z += v.z; s.w += v.w;
            }
            g_part4[((b * CH + chunk) * 3 + kk) * ND4 + dd] = s;
        }
    }
}

// ---------------------------------------------------------------------------
// Kernel 2: sim = conv(g) + conv_b*S_k + b_k  -> g_h.
// grid (4 ctiles, 16 btiles), 128 threads = 32 channel-lanes x 4 batch-warps.
// Per-thread private dot products (no shuffles). conv_w tile in smem.
// Dynamic smem: cw[2400 f4] + sg[900 f4] = 52800 B.
// ---------------------------------------------------------------------------
__global__ __launch_bounds__(128) void sim_kernel(
    const float* __restrict__ conv_w,
    const float* __restrict__ conv_b,
    const float* __restrict__ fc3_w,
    const float* __restrict__ fc3_b,
    const float* __restrict__ fc4_w,
    const float* __restrict__ fc4_b,
    const float* __restrict__ fc5_w,
    const float* __restrict__ fc5_b)
{
    extern __shared__ float4 dyn[];
    float4* cw_s = dyn;            // [32][75]
    float4* sg   = dyn + 2400;     // [4][3*75] (kk-major within 225)
    __shared__ float sSk[3];

    const int tid  = threadIdx.x;
    const int warp = tid >> 5;
    const int lane = tid & 31;
    const int c0 = blockIdx.x * 32;
    const int b0 = blockIdx.y * 4;

    // S_k (warps 0-2; tiny)
    if (warp < 3) {
        const float* wks[3] = {fc3_w, fc4_w, fc5_w};
        const float* w = wks[warp];
        const int n = NL - (warp + 3);
        float s = 0.f;
        for (int l = lane; l < n; l += 32) s += w[l];
        #pragma unroll
        for (int off = 16; off > 0; off >>= 1)
            s += __shfl_xor_sync(0xFFFFFFFFu, s, off);
        if (lane == 0) sSk[warp] = s;
    }

    // Stage conv_w tile (rows c0..c0+31), fully coalesced
    {
        const float4* cwg = (const float4*)conv_w;
        #pragma unroll
        for (int j = tid; j < 32 * ND4; j += 128)
            cw_s[j] = __ldg(&cwg[c0 * ND4 + j]);
    }

    // Reduce g_part chunks -> sg[bsub][225]
    for (int pos = tid; pos < 4 * 225; pos += 128) {
        const int bsub = pos / 225;
        const int i    = pos % 225;
        const float4* p = &g_part4[(b0 + bsub) * CH * 225 + i];
        float4 s = p[0];
        #pragma unroll
        for (int ch = 1; ch < CH; ch++) {
            const float4 v = p[ch * 225];
            s.x += v.x; s.y += v.y; s.z += v.z; s.w += v.w;
        }
        sg[bsub * 225 + i] = s;
    }
    __syncthreads();

    // Private dots: thread (c=lane, bsub=warp)
    const int c    = lane;
    const int bsub = warp;
    float s0 = 0.f, s1 = 0.f, s2 = 0.f;
    #pragma unroll 5
    for (int i = 0; i < ND4; i++) {
        const float4 w  = cw_s[c * ND4 + i];           // conflict-free (stride 75 f4)
        const float4 g0 = sg[bsub * 225 + i];          // broadcast
        const float4 g1 = sg[bsub * 225 + 75 + i];
        const float4 g2 = sg[bsub * 225 + 150 + i];
        s0 = fmaf(w.x, g0.x, s0); s0 = fmaf(w.y, g0.y, s0);
        s0 = fmaf(w.z, g0.z, s0); s0 = fmaf(w.w, g0.w, s0);
        s1 = fmaf(w.x, g1.x, s1); s1 = fmaf(w.y, g1.y, s1);
        s1 = fmaf(w.z, g1.z, s1); s1 = fmaf(w.w, g1.w, s1);
        s2 = fmaf(w.x, g2.x, s2); s2 = fmaf(w.y, g2.y, s2);
        s2 = fmaf(w.z, g2.z, s2); s2 = fmaf(w.w, g2.w, s2);
    }

    const float cb = conv_b[c0 + c];
    const int b = b0 + bsub;
    float* h = (float*)g_h4;                // h[b][384]
    h[b * 384 + 0 * NC + c0 + c] = s0 + cb * sSk[0] + fc3_b[0];
    h[b * 384 + 1 * NC + c0 + c] = s1 + cb * sSk[1] + fc4_b[0];
    h[b * 384 + 2 * NC + c0 + c] = s2 + cb * sSk[2] + fc5_b[0];
}

// ---------------------------------------------------------------------------
// Kernel 3: out = h @ fc_w^T + fc_b.
// grid (4 cotiles, 16 btiles), 128 threads = 32 co-lanes x 4 batch-warps.
// fc_w tile rows padded to 97 f4 in smem (96 would be 32-way bank conflict).
// Dynamic smem: fw[32*97 f4] + sh[384 f4] = 55808 B.
// ---------------------------------------------------------------------------
__global__ __launch_bounds__(128) void fc_kernel(
    const float* __restrict__ fc_w,
    const float* __restrict__ fc_b,
    float* __restrict__ out)
{
    extern __shared__ float4 dyn[];
    float4* fw_s = dyn;            // [32][97] (padded)
    float4* sh   = dyn + 32 * 97;  // [4][96]

    const int tid = threadIdx.x;
    const int c0 = blockIdx.x * 32;
    const int b0 = blockIdx.y * 4;

    {
        const float4* fwg = (const float4*)fc_w;
        #pragma unroll
        for (int j = tid; j < 32 * 96; j += 128) {
            const int r = j / 96, i = j % 96;
            fw_s[r * 97 + i] = __ldg(&fwg[(c0 + r) * 96 + i]);
        }
        #pragma unroll
        for (int j = tid; j < 4 * 96; j += 128)
            sh[j] = g_h4[b0 * 96 + j];
    }
    __syncthreads();

    const int co   = tid & 31;
    const int bsub = tid >> 5;
    float o = 0.f;
    #pragma unroll 8
    for (int i = 0; i < 96; i++) {
        const float4 w = fw_s[co * 97 + i];    // conflict-free (stride 97 f4)
        const float4 h = sh[bsub * 96 + i];    // broadcast
        o = fmaf(w.x, h.x, o); o = fmaf(w.y, h.y, o);
        o = fmaf(w.z, h.z, o); o = fmaf(w.w, h.w, o);
    }
    out[(b0 + bsub) * NC + c0 + co] = o + fc_b[c0 + co];
}

// ---------------------------------------------------------------------------
extern "C" void kernel_launch(void* const* d_in, const int* in_sizes, int n_in,
                              void* d_out, int out_size) {
    const int*   x       = (const int*)  d_in[0];
    const float* embed_w = (const float*)d_in[1];
    const float* conv_w  = (const float*)d_in[2];
    const float* conv_b  = (const float*)d_in[3];
    const float* fc3_w   = (const float*)d_in[4];
    const float* fc3_b   = (const float*)d_in[5];
    const float* fc4_w   = (const float*)d_in[6];
    const float* fc4_b   = (const float*)d_in[7];
    const float* fc5_w   = (const float*)d_in[8];
    const float* fc5_b   = (const float*)d_in[9];
    const float* fc_w    = (const float*)d_in[10];
    const float* fc_b    = (const float*)d_in[11];
    float* out = (float*)d_out;

    const int sim_smem = (2400 + 900) * (int)sizeof(float4);      // 52800
    const int fc_smem  = (32 * 97 + 384) * (int)sizeof(float4);   // 55808
    cudaFuncSetAttribute(sim_kernel, cudaFuncAttributeMaxDynamicSharedMemorySize, sim_smem);
    cudaFuncSetAttribute(fc_kernel,  cudaFuncAttributeMaxDynamicSharedMemorySize, fc_smem);

    gather_kernel<<<NB * CH, 320>>>(x, embed_w, fc3_w, fc4_w, fc5_w);
    sim_kernel<<<dim3(4, 16), 128, sim_smem>>>(conv_w, conv_b, fc3_w, fc3_b,
                                               fc4_w, fc4_b, fc5_w, fc5_b);
    fc_kernel<<<dim3(4, 16), 128, fc_smem>>>(fc_w, fc_b, out);
}